// round 1
// baseline (speedup 1.0000x reference)
#include <cuda_runtime.h>
#include <cstdint>

#define WID 256
#define HGT 256
#define HW  65536
#define BATCH 8
#define BHW 524288  // 8*256*256

// ---------------- scratch (no cudaMalloc allowed) ----------------
__device__ float g_vs[BHW];               // V / sf      (input to conv1)
__device__ float g_a1[BATCH * 32 * HW];   // conv1 out, reused for conv3 out
__device__ float g_a2[BATCH * 64 * HW];   // conv2 out

// ---------------- kernel 1: elementwise + laplacian ----------------
// out layout (tuple flatten-concat):
//   [0*BHW) outputs  [1*BHW) H  [2*BHW) C_new(B,2,H,W)  [4*BHW) V  [5*BHW) V_hat
__global__ void __launch_bounds__(256) prep_kernel(
    const float* __restrict__ inp, const float* __restrict__ H0,
    const float* __restrict__ C0, const float* __restrict__ c2,
    const float* __restrict__ sf, float* __restrict__ out,
    float* __restrict__ vs)
{
    int idx = blockIdx.x * 256 + threadIdx.x;
    if (idx >= BHW) return;
    int b   = idx >> 16;
    int rem = idx & 65535;
    int y   = rem >> 8;
    int x   = rem & 255;

    float c  = inp[idx];
    float up = (y > 0)       ? inp[idx - WID] : 0.f;
    float dn = (y < HGT - 1) ? inp[idx + WID] : 0.f;
    float lf = (x > 0)       ? inp[idx - 1]   : 0.f;
    float rt = (x < WID - 1) ? inp[idx + 1]   : 0.f;
    float lap = up + dn + lf + rt - 4.f * c;

    float c0v = C0[(size_t)b * 2 * HW + rem];
    float Hv  = 2.f * c - c0v + c2[0] * lap;
    float V   = c - H0[idx];

    out[(size_t)BHW + idx]     = Hv;                  // H
    out[4 * (size_t)BHW + idx] = V;                   // V
    out[2 * (size_t)BHW + (size_t)b * 2 * HW + rem]      = c;    // C_new[:,0]
    out[2 * (size_t)BHW + (size_t)b * 2 * HW + HW + rem] = c0v;  // C_new[:,1]
    vs[idx] = V / sf[0];
}

// ---------------- generic 3x3 SAME conv + bias + relu ----------------
// in  : [B, CIN, 256, 256]   wgt: [COUT, CIN, 3, 3]   out: [B, COUT, 256, 256]
// CTA tile: 32x8 output pixels. 256 threads = 64 pixel-groups (4 px each,
// x-contiguous) x 4 channel-groups (CO_T = COUT/4 channels each).
template <int CIN, int COUT>
__global__ void __launch_bounds__(256, 1) conv3x3_relu(
    const float* __restrict__ in, const float* __restrict__ wgt,
    const float* __restrict__ bias, float* __restrict__ out)
{
    constexpr int CO_T     = COUT / 4;
    constexpr int IN_ELEMS = CIN * 10 * 34;   // tile with 1-px halo
    constexpr int W_ELEMS  = CIN * 9 * COUT;
    extern __shared__ float smem[];
    float* s_in = smem;
    float* s_w  = smem + IN_ELEMS;            // layout [ci][k][co] for float4 co reads

    const int b  = blockIdx.z;
    const int x0 = blockIdx.x * 32;
    const int y0 = blockIdx.y * 8;
    const int t  = threadIdx.x;

    const float* inb = in + (size_t)b * CIN * HW;
    for (int i = t; i < IN_ELEMS; i += 256) {
        int ci = i / 340;
        int r  = i - ci * 340;
        int yy = r / 34;
        int xx = r - yy * 34;
        int gy = y0 + yy - 1;
        int gx = x0 + xx - 1;
        float v = 0.f;
        if ((unsigned)gy < HGT && (unsigned)gx < WID)
            v = inb[(size_t)ci * HW + gy * WID + gx];
        s_in[i] = v;
    }
    for (int i = t; i < W_ELEMS; i += 256) {
        int co = i % COUT;
        int r  = i / COUT;
        int k  = r % 9;
        int ci = r / 9;
        s_w[i] = wgt[((size_t)co * CIN + ci) * 9 + k];
    }
    __syncthreads();

    const int pg  = t & 63;
    const int cg  = t >> 6;
    const int px  = (pg & 7) * 4;  // 0..28
    const int py  = pg >> 3;       // 0..7
    const int co0 = cg * CO_T;

    float acc[4][CO_T];
    #pragma unroll
    for (int p = 0; p < 4; p++)
        #pragma unroll
        for (int c = 0; c < CO_T; c++) acc[p][c] = 0.f;

    #pragma unroll 1
    for (int ci = 0; ci < CIN; ci++) {
        const float* si = s_in + ci * 340 + py * 34 + px;
        float xr[3][6];
        #pragma unroll
        for (int ky = 0; ky < 3; ky++)
            #pragma unroll
            for (int dx = 0; dx < 6; dx++)
                xr[ky][dx] = si[ky * 34 + dx];

        const float* wp = s_w + ci * 9 * COUT + co0;
        #pragma unroll
        for (int ky = 0; ky < 3; ky++) {
            #pragma unroll
            for (int kx = 0; kx < 3; kx++) {
                const float4* wv4 = (const float4*)(wp + (ky * 3 + kx) * COUT);
                #pragma unroll
                for (int cv = 0; cv < CO_T / 4; cv++) {
                    float4 wv = wv4[cv];
                    #pragma unroll
                    for (int p = 0; p < 4; p++) {
                        float xv = xr[ky][kx + p];
                        acc[p][cv * 4 + 0] = fmaf(xv, wv.x, acc[p][cv * 4 + 0]);
                        acc[p][cv * 4 + 1] = fmaf(xv, wv.y, acc[p][cv * 4 + 1]);
                        acc[p][cv * 4 + 2] = fmaf(xv, wv.z, acc[p][cv * 4 + 2]);
                        acc[p][cv * 4 + 3] = fmaf(xv, wv.w, acc[p][cv * 4 + 3]);
                    }
                }
            }
        }
    }

    float* outb = out + (size_t)b * COUT * HW + (size_t)(y0 + py) * WID + (x0 + px);
    #pragma unroll
    for (int c = 0; c < CO_T; c++) {
        float bv = bias[co0 + c];
        float4 o;
        o.x = fmaxf(acc[0][c] + bv, 0.f);
        o.y = fmaxf(acc[1][c] + bv, 0.f);
        o.z = fmaxf(acc[2][c] + bv, 0.f);
        o.w = fmaxf(acc[3][c] + bv, 0.f);
        *(float4*)(outb + (size_t)(co0 + c) * HW) = o;
    }
}

// ---------------- conv4 (32->1) fused with *sf, V_hat, outputs = H + V_hat ----
// Same tiling; the 4 channel-groups each cover 8 input channels and the partials
// are reduced through SMEM.
__global__ void __launch_bounds__(256, 1) conv4_final(
    const float* __restrict__ a3, const float* __restrict__ w4,
    const float* __restrict__ b4, const float* __restrict__ sf,
    float* __restrict__ out)
{
    constexpr int IN_ELEMS = 32 * 340;
    extern __shared__ float smem[];
    float* s_in  = smem;
    float* s_w   = smem + IN_ELEMS;      // 288
    float* s_red = s_w + 288;            // 256*4

    const int b  = blockIdx.z;
    const int x0 = blockIdx.x * 32;
    const int y0 = blockIdx.y * 8;
    const int t  = threadIdx.x;

    const float* inb = a3 + (size_t)b * 32 * HW;
    for (int i = t; i < IN_ELEMS; i += 256) {
        int ci = i / 340;
        int r  = i - ci * 340;
        int yy = r / 34;
        int xx = r - yy * 34;
        int gy = y0 + yy - 1;
        int gx = x0 + xx - 1;
        float v = 0.f;
        if ((unsigned)gy < HGT && (unsigned)gx < WID)
            v = inb[(size_t)ci * HW + gy * WID + gx];
        s_in[i] = v;
    }
    for (int i = t; i < 288; i += 256) s_w[i] = w4[i];  // [1,32,3,3] -> ci*9+k
    __syncthreads();

    const int pg = t & 63;
    const int cg = t >> 6;
    const int px = (pg & 7) * 4;
    const int py = pg >> 3;

    float acc[4] = {0.f, 0.f, 0.f, 0.f};
    #pragma unroll 1
    for (int ci = cg * 8; ci < cg * 8 + 8; ci++) {
        const float* si = s_in + ci * 340 + py * 34 + px;
        float xr[3][6];
        #pragma unroll
        for (int ky = 0; ky < 3; ky++)
            #pragma unroll
            for (int dx = 0; dx < 6; dx++)
                xr[ky][dx] = si[ky * 34 + dx];
        #pragma unroll
        for (int ky = 0; ky < 3; ky++)
            #pragma unroll
            for (int kx = 0; kx < 3; kx++) {
                float wv = s_w[ci * 9 + ky * 3 + kx];
                #pragma unroll
                for (int p = 0; p < 4; p++)
                    acc[p] = fmaf(xr[ky][kx + p], wv, acc[p]);
            }
    }
    #pragma unroll
    for (int p = 0; p < 4; p++) s_red[(cg * 64 + pg) * 4 + p] = acc[p];
    __syncthreads();

    if (t < 64) {  // cg == 0, pg == t
        float sfv = sf[0], b4v = b4[0];
        int y  = y0 + (t >> 3);
        int xb = x0 + (t & 7) * 4;
        size_t idx = (size_t)b * HW + (size_t)y * WID + xb;
        float vh[4];
        #pragma unroll
        for (int p = 0; p < 4; p++) {
            float s = s_red[t * 4 + p] + s_red[(64 + t) * 4 + p] +
                      s_red[(128 + t) * 4 + p] + s_red[(192 + t) * 4 + p];
            vh[p] = (s + b4v) * sfv;
        }
        float4 v4 = {vh[0], vh[1], vh[2], vh[3]};
        *(float4*)(out + 5 * (size_t)BHW + idx) = v4;          // V_hat
        const float4 h4 = *(const float4*)(out + (size_t)BHW + idx);  // H
        float4 o4 = {h4.x + vh[0], h4.y + vh[1], h4.z + vh[2], h4.w + vh[3]};
        *(float4*)(out + idx) = o4;                            // outputs
    }
}

// ---------------- launch ----------------
extern "C" void kernel_launch(void* const* d_in, const int* in_sizes, int n_in,
                              void* d_out, int out_size)
{
    const float* inputs = (const float*)d_in[0];
    const float* H0     = (const float*)d_in[1];
    const float* C0     = (const float*)d_in[2];
    const float* c2     = (const float*)d_in[3];
    const float* sf     = (const float*)d_in[4];
    const float* w1     = (const float*)d_in[5];
    const float* b1     = (const float*)d_in[6];
    const float* w2     = (const float*)d_in[7];
    const float* b2     = (const float*)d_in[8];
    const float* w3     = (const float*)d_in[9];
    const float* b3     = (const float*)d_in[10];
    const float* w4     = (const float*)d_in[11];
    const float* b4     = (const float*)d_in[12];
    float* out = (float*)d_out;

    float *vs, *a1, *a2;
    cudaGetSymbolAddress((void**)&vs, g_vs);
    cudaGetSymbolAddress((void**)&a1, g_a1);
    cudaGetSymbolAddress((void**)&a2, g_a2);

    const size_t SM1 = (1 * 340 + 1 * 9 * 32) * sizeof(float);    // 2.5 KB
    const size_t SM2 = (32 * 340 + 32 * 9 * 64) * sizeof(float);  // 117248 B
    const size_t SM3 = (64 * 340 + 64 * 9 * 32) * sizeof(float);  // 160768 B
    const size_t SM4 = (32 * 340 + 288 + 1024) * sizeof(float);   // 48768 B

    cudaFuncSetAttribute(conv3x3_relu<32, 64>,
                         cudaFuncAttributeMaxDynamicSharedMemorySize, (int)SM2);
    cudaFuncSetAttribute(conv3x3_relu<64, 32>,
                         cudaFuncAttributeMaxDynamicSharedMemorySize, (int)SM3);
    cudaFuncSetAttribute(conv4_final,
                         cudaFuncAttributeMaxDynamicSharedMemorySize, (int)SM4);

    prep_kernel<<<BHW / 256, 256>>>(inputs, H0, C0, c2, sf, out, vs);

    dim3 cgrid(WID / 32, HGT / 8, BATCH);  // (8, 32, 8)
    conv3x3_relu<1, 32><<<cgrid, 256, SM1>>>(vs, w1, b1, a1);
    conv3x3_relu<32, 64><<<cgrid, 256, SM2>>>(a1, w2, b2, a2);
    conv3x3_relu<64, 32><<<cgrid, 256, SM3>>>(a2, w3, b3, a1);
    conv4_final<<<cgrid, 256, SM4>>>(a1, w4, b4, sf, out);
}